// round 16
// baseline (speedup 1.0000x reference)
#include <cuda_runtime.h>
#include <cuda_bf16.h>
#include <cstdint>

#define DIM   192
#define HEADS 6
#define HDIM  32
#define NTOK  64
#define NWIN  4096

// ---------------------------------------------------------------------------
// Scratch (static device globals — no allocation in kernel_launch)
// ---------------------------------------------------------------------------
__device__ __nv_bfloat16 g_qkvh[(size_t)NWIN * 3 * HEADS * NTOK * HDIM];
__device__ __nv_bfloat16 g_qkvl[(size_t)NWIN * 3 * HEADS * NTOK * HDIM];
__device__ __nv_bfloat16 g_atth[(size_t)NWIN * NTOK * DIM];
__device__ __nv_bfloat16 g_attl[(size_t)NWIN * NTOK * DIM];
__device__ float g_bias[HEADS * NTOK * NTOK];
// pre-split weights: [plane hi/lo][col][k] bf16, k contiguous
__device__ __nv_bfloat16 g_wq[2][576 * 192];
__device__ __nv_bfloat16 g_wp[2][192 * 192];

// ---------------------------------------------------------------------------
// Helpers
// ---------------------------------------------------------------------------
__device__ __forceinline__ uint32_t smem_to_u32(const void* smem_ptr) {
    uint32_t addr;
    asm("{ .reg .u64 tmp; cvta.to.shared.u64 tmp, %1; cvt.u32.u64 %0, tmp; }"
        : "=r"(addr) : "l"(smem_ptr));
    return addr;
}
__device__ __forceinline__ void ldm_x4(uint32_t* r, uint32_t addr) {
    asm volatile("ldmatrix.sync.aligned.m8n8.x4.shared.b16 {%0,%1,%2,%3}, [%4];"
                 : "=r"(r[0]), "=r"(r[1]), "=r"(r[2]), "=r"(r[3]) : "r"(addr));
}
__device__ __forceinline__ void ldm_x4_t(uint32_t* r, uint32_t addr) {
    asm volatile("ldmatrix.sync.aligned.m8n8.x4.trans.shared.b16 {%0,%1,%2,%3}, [%4];"
                 : "=r"(r[0]), "=r"(r[1]), "=r"(r[2]), "=r"(r[3]) : "r"(addr));
}
__device__ __forceinline__ void mma16816(float* c, const uint32_t* a,
                                         uint32_t b0, uint32_t b1) {
    asm volatile(
        "mma.sync.aligned.m16n8k16.row.col.f32.bf16.bf16.f32 "
        "{%0,%1,%2,%3}, {%4,%5,%6,%7}, {%8,%9}, {%0,%1,%2,%3};"
        : "+f"(c[0]), "+f"(c[1]), "+f"(c[2]), "+f"(c[3])
        : "r"(a[0]), "r"(a[1]), "r"(a[2]), "r"(a[3]), "r"(b0), "r"(b1));
}
__device__ __forceinline__ void cp16(uint32_t saddr, const void* gptr) {
    asm volatile("cp.async.cg.shared.global [%0], [%1], 16;"
                 :: "r"(saddr), "l"(gptr));
}
#define CP_COMMIT() asm volatile("cp.async.commit_group;" ::: "memory")
#define CP_WAIT0()  asm volatile("cp.async.wait_group 0;" ::: "memory")
#define CP_WAIT1()  asm volatile("cp.async.wait_group 1;" ::: "memory")

// bf16 hi/lo split of 4 floats, packed for 8-byte smem stores
__device__ __forceinline__ void split4(float4 v, uint2& hi, uint2& lo) {
    __nv_bfloat16 hx = __float2bfloat16(v.x), hy = __float2bfloat16(v.y);
    __nv_bfloat16 hz = __float2bfloat16(v.z), hw = __float2bfloat16(v.w);
    float rx = v.x - __bfloat162float(hx), ry = v.y - __bfloat162float(hy);
    float rz = v.z - __bfloat162float(hz), rw = v.w - __bfloat162float(hw);
    __nv_bfloat16 lx = __float2bfloat16(rx), ly = __float2bfloat16(ry);
    __nv_bfloat16 lz = __float2bfloat16(rz), lw = __float2bfloat16(rw);
    hi.x = (uint32_t)__bfloat16_as_ushort(hx) | ((uint32_t)__bfloat16_as_ushort(hy) << 16);
    hi.y = (uint32_t)__bfloat16_as_ushort(hz) | ((uint32_t)__bfloat16_as_ushort(hw) << 16);
    lo.x = (uint32_t)__bfloat16_as_ushort(lx) | ((uint32_t)__bfloat16_as_ushort(ly) << 16);
    lo.y = (uint32_t)__bfloat16_as_ushort(lz) | ((uint32_t)__bfloat16_as_ushort(lw) << 16);
}
__device__ __forceinline__ uint32_t pack_bf16_pair(float a, float b) {
    __nv_bfloat16 ha = __float2bfloat16(a), hb = __float2bfloat16(b);
    return (uint32_t)__bfloat16_as_ushort(ha) | ((uint32_t)__bfloat16_as_ushort(hb) << 16);
}
__device__ __forceinline__ void store_split2(float v0, float v1,
                                             __nv_bfloat16* hp, __nv_bfloat16* lp) {
    __nv_bfloat16 h0 = __float2bfloat16(v0), h1 = __float2bfloat16(v1);
    float l0 = v0 - __bfloat162float(h0), l1 = v1 - __bfloat162float(h1);
    __nv_bfloat162 hv; hv.x = h0; hv.y = h1;
    __nv_bfloat162 lv; lv.x = __float2bfloat16(l0); lv.y = __float2bfloat16(l1);
    *(__nv_bfloat162*)hp = hv;
    *(__nv_bfloat162*)lp = lv;
}

// ---------------------------------------------------------------------------
// K0a: bias materialization
// ---------------------------------------------------------------------------
__global__ void bias_kernel(const float* __restrict__ rpb,
                            const int*   __restrict__ rel_idx) {
    int idx = blockIdx.x * blockDim.x + threadIdx.x;
    if (idx < HEADS * NTOK * NTOK) {
        int h = idx / (NTOK * NTOK);
        int r = idx % (NTOK * NTOK);
        g_bias[idx] = rpb[rel_idx[r] * HEADS + h];
    }
}
// K0b: weight hi/lo split
__global__ void wsplit_kernel(const float* __restrict__ qkv_w,
                              const float* __restrict__ proj_w) {
    int idx = blockIdx.x * blockDim.x + threadIdx.x;
    if (idx < 576 * 192) {
        float w = qkv_w[idx];
        __nv_bfloat16 hi = __float2bfloat16(w);
        g_wq[0][idx] = hi;
        g_wq[1][idx] = __float2bfloat16(w - __bfloat162float(hi));
    }
    if (idx < 192 * 192) {
        float w = proj_w[idx];
        __nv_bfloat16 hi = __float2bfloat16(w);
        g_wp[0][idx] = hi;
        g_wp[1][idx] = __float2bfloat16(w - __bfloat162float(hi));
    }
}

// ---------------------------------------------------------------------------
// GEMM shared layout: pitch 400B (192 bf16 + 8 pad)
// ---------------------------------------------------------------------------
#define PITCH      400u
#define A_LO_OFF   51200u
#define B_BASE     102400u
#define B_LO_OFF   25600u
#define B_STRIDE   51200u
#define SMEM_BYTES 204800u

// ---------------------------------------------------------------------------
// GEMM (R13-proven shape): 256 threads, 8 warps as 4x2, warp tile 32x32.
// C[128 rows, CT*64 cols] = A(.,192) @ W^T + b  (bf16 hi/lo, 3 products)
// QKV=true: A=x fp32 (split in-kernel), epilogue -> g_qkvh/l (q scaled).
// QKV=false: A=g_atth/l via cp.async, epilogue -> fp32 Out.
// ---------------------------------------------------------------------------
template<int CT, bool QKV>
__global__ void __launch_bounds__(256, 1)
gemm_kernel(const float* __restrict__ Ain,
            const float* __restrict__ bvec, float* __restrict__ Out)
{
    extern __shared__ __align__(16) char smem[];
    const uint32_t sb = smem_to_u32(smem);
    const int tid = threadIdx.x;
    const int wid = tid >> 5, lid = tid & 31;
    const int rowBase = blockIdx.x * 128;
    const int warpRow = (wid & 3) * 32;
    const int warpCol = (wid >> 2) * 32;

    const __nv_bfloat16* whi = QKV ? g_wq[0] : g_wp[0];
    const __nv_bfloat16* wlo = QKV ? g_wq[1] : g_wp[1];

    // prologue: cp.async B tile 0 into stage 0 (3072 cp16)
#pragma unroll
    for (int i = 0; i < 12; i++) {
        int idx = tid + i * 256;
        int plane = idx / 1536, rem = idx - plane * 1536;
        int r = rem / 24, c = rem % 24;
        const __nv_bfloat16* src = (plane ? wlo : whi) + (size_t)r * 192 + c * 8;
        cp16(sb + B_BASE + plane * B_LO_OFF + r * PITCH + c * 16, src);
    }

    // A tile
    if (QKV) {
#pragma unroll
        for (int i = 0; i < 24; i++) {
            int idx = tid + i * 256;
            int r = idx / 48, k4 = (idx % 48) * 4;
            float4 v = *(const float4*)(Ain + (size_t)(rowBase + r) * DIM + k4);
            uint2 hi, lo; split4(v, hi, lo);
            *(uint2*)(smem + r * PITCH + k4 * 2) = hi;
            *(uint2*)(smem + A_LO_OFF + r * PITCH + k4 * 2) = lo;
        }
    } else {
#pragma unroll
        for (int i = 0; i < 24; i++) {
            int idx = tid + i * 256;              // 6144 cp16
            int plane = idx / 3072, rem = idx - plane * 3072;
            int r = rem / 24, c = rem % 24;
            const __nv_bfloat16* src =
                (plane ? g_attl : g_atth) + (size_t)(rowBase + r) * 192 + c * 8;
            cp16(sb + plane * A_LO_OFF + r * PITCH + c * 16, src);
        }
    }
    CP_COMMIT();
    CP_WAIT0();
    __syncthreads();

    const int lrow = (lid & 7) + ((lid >> 3) & 1) * 8;
    const int lkb  = (lid >> 4) * 16;
    const uint32_t aoff0 = (uint32_t)((warpRow + lrow) * PITCH) + lkb;
    const uint32_t aoff1 = aoff0 + 16 * PITCH;
    const uint32_t boff0 = (uint32_t)((warpCol + lrow) * PITCH) + lkb;
    const uint32_t boff1 = boff0 + 16 * PITCH;

    for (int ct = 0; ct < CT; ct++) {
        if (ct + 1 < CT) {
#pragma unroll
            for (int i = 0; i < 12; i++) {
                int idx = tid + i * 256;
                int plane = idx / 1536, rem = idx - plane * 1536;
                int r = rem / 24, c = rem % 24;
                const __nv_bfloat16* src =
                    (plane ? wlo : whi) + (size_t)((ct + 1) * 64 + r) * 192 + c * 8;
                cp16(sb + B_BASE + (uint32_t)((ct + 1) & 1) * B_STRIDE
                        + plane * B_LO_OFF + r * PITCH + c * 16, src);
            }
            CP_COMMIT();
        }

        float acc[2][4][4];
#pragma unroll
        for (int mt = 0; mt < 2; mt++)
#pragma unroll
            for (int nt = 0; nt < 4; nt++)
#pragma unroll
                for (int e = 0; e < 4; e++) acc[mt][nt][e] = 0.0f;

        const uint32_t bbh = sb + B_BASE + (uint32_t)(ct & 1) * B_STRIDE;
        const uint32_t bbl = bbh + B_LO_OFF;
#pragma unroll
        for (int ks = 0; ks < 12; ks++) {
            uint32_t Ah0[4], Ah1[4], Al0[4], Al1[4];
            uint32_t Bh0[4], Bh1[4], Bl0[4], Bl1[4];
            ldm_x4(Ah0, sb + aoff0 + ks * 32);
            ldm_x4(Ah1, sb + aoff1 + ks * 32);
            ldm_x4(Al0, sb + A_LO_OFF + aoff0 + ks * 32);
            ldm_x4(Al1, sb + A_LO_OFF + aoff1 + ks * 32);
            ldm_x4(Bh0, bbh + boff0 + ks * 32);
            ldm_x4(Bh1, bbh + boff1 + ks * 32);
            ldm_x4(Bl0, bbl + boff0 + ks * 32);
            ldm_x4(Bl1, bbl + boff1 + ks * 32);
            mma16816(acc[0][0], Ah0, Bh0[0], Bh0[2]);
            mma16816(acc[0][1], Ah0, Bh0[1], Bh0[3]);
            mma16816(acc[0][2], Ah0, Bh1[0], Bh1[2]);
            mma16816(acc[0][3], Ah0, Bh1[1], Bh1[3]);
            mma16816(acc[1][0], Ah1, Bh0[0], Bh0[2]);
            mma16816(acc[1][1], Ah1, Bh0[1], Bh0[3]);
            mma16816(acc[1][2], Ah1, Bh1[0], Bh1[2]);
            mma16816(acc[1][3], Ah1, Bh1[1], Bh1[3]);
            mma16816(acc[0][0], Ah0, Bl0[0], Bl0[2]);
            mma16816(acc[0][1], Ah0, Bl0[1], Bl0[3]);
            mma16816(acc[0][2], Ah0, Bl1[0], Bl1[2]);
            mma16816(acc[0][3], Ah0, Bl1[1], Bl1[3]);
            mma16816(acc[1][0], Ah1, Bl0[0], Bl0[2]);
            mma16816(acc[1][1], Ah1, Bl0[1], Bl0[3]);
            mma16816(acc[1][2], Ah1, Bl1[0], Bl1[2]);
            mma16816(acc[1][3], Ah1, Bl1[1], Bl1[3]);
            mma16816(acc[0][0], Al0, Bh0[0], Bh0[2]);
            mma16816(acc[0][1], Al0, Bh0[1], Bh0[3]);
            mma16816(acc[0][2], Al0, Bh1[0], Bh1[2]);
            mma16816(acc[0][3], Al0, Bh1[1], Bh1[3]);
            mma16816(acc[1][0], Al1, Bh0[0], Bh0[2]);
            mma16816(acc[1][1], Al1, Bh0[1], Bh0[3]);
            mma16816(acc[1][2], Al1, Bh1[0], Bh1[2]);
            mma16816(acc[1][3], Al1, Bh1[1], Bh1[3]);
        }

        // epilogue
        const int g  = lid >> 2;
        const int c2 = (lid & 3) * 2;
#pragma unroll
        for (int mt = 0; mt < 2; mt++) {
            const int r0 = rowBase + warpRow + mt * 16 + g;
#pragma unroll
            for (int nt = 0; nt < 4; nt++) {
                const int colg = ct * 64 + warpCol + nt * 8 + c2;
                const float bv0 = bvec[colg], bv1 = bvec[colg + 1];
                if (QKV) {
                    const int s = colg / DIM, rem = colg % DIM;
                    const int h = rem >> 5, dd = rem & 31;
                    const float mul = (s == 0) ? 0.17677669529663687f : 1.0f;
#pragma unroll
                    for (int hh = 0; hh < 2; hh++) {
                        const int row = r0 + hh * 8;
                        const int bw = row >> 6, n = row & 63;
                        size_t base = ((((size_t)bw * 3 + s) * HEADS + h) * NTOK + n) * HDIM + dd;
                        store_split2((acc[mt][nt][hh * 2 + 0] + bv0) * mul,
                                     (acc[mt][nt][hh * 2 + 1] + bv1) * mul,
                                     g_qkvh + base, g_qkvl + base);
                    }
                } else {
#pragma unroll
                    for (int hh = 0; hh < 2; hh++) {
                        const int row = r0 + hh * 8;
                        float2 o = make_float2(acc[mt][nt][hh * 2 + 0] + bv0,
                                               acc[mt][nt][hh * 2 + 1] + bv1);
                        *(float2*)(Out + (size_t)row * DIM + colg) = o;
                    }
                }
            }
        }
        if (ct + 1 < CT) {
            CP_WAIT0();
            __syncthreads();
        }
    }
}

// ---------------------------------------------------------------------------
// Pipelined attention: one block per WINDOW (grid 4096, 128 thr, 4 warps),
// loop over 6 heads with double-buffered q/k/v plane stages (cp.async).
// Stage layout (bytes, per stage 30720): q@0, k@10240, v@20480, lo +5120.
// P planes at 61440 (hi) / 70656 (lo), pitch 144.
// ---------------------------------------------------------------------------
#define ASTAGE   30720u
#define APL_HALF 5120u
#define AK_OFF   10240u
#define AV_OFF   20480u
#define AP_HI    61440u
#define AP_LO    70656u
#define ATT_SMEM 79872u
#define VPITCH 80u
#define PPITCH 144u

__device__ __forceinline__ void attn_prefetch(uint32_t dst, int b, int hh, int tid) {
#pragma unroll
    for (int i = 0; i < 12; i++) {
        int idx = tid + i * 128;               // 1536 cp16
        int plane = idx >> 8;                  // 6 planes x 256 cp16
        int rem = idx & 255;
        int n = rem >> 2, c = rem & 3;
        int mat = plane >> 1, lo = plane & 1;
        const __nv_bfloat16* src =
            (lo ? g_qkvl : g_qkvh) +
            ((((size_t)b * 3 + mat) * HEADS + hh) * NTOK + n) * HDIM + c * 8;
        cp16(dst + (uint32_t)mat * 10240u + (uint32_t)lo * APL_HALF
                + (uint32_t)n * VPITCH + (uint32_t)c * 16u, src);
    }
}

__global__ void __launch_bounds__(128) attn_kernel() {
    extern __shared__ __align__(16) char smem[];
    const uint32_t sb = smem_to_u32(smem);
    const int tid = threadIdx.x;
    const int wid = tid >> 5, lid = tid & 31;
    const int b = blockIdx.x;

    const int warpRow = wid * 16;
    const int lrow = (lid & 7) + ((lid >> 3) & 1) * 8;
    const int lkb  = (lid >> 4) * 16;
    const int g  = lid >> 2;
    const int c2 = (lid & 3) * 2;

    // prologue: prefetch head 0 into stage 0
    attn_prefetch(sb, b, 0, tid);
    CP_COMMIT();

    for (int h = 0; h < HEADS; h++) {
        const uint32_t st = sb + (uint32_t)(h & 1) * ASTAGE;
        if (h + 1 < HEADS) {
            attn_prefetch(sb + (uint32_t)((h + 1) & 1) * ASTAGE, b, h + 1, tid);
            CP_COMMIT();
            CP_WAIT1();
        } else {
            CP_WAIT0();
        }
        __syncthreads();

        // ---- S = q.k^T + bias ----
        float acc[8][4];
        {
            const float* bias = g_bias + h * (NTOK * NTOK);
            const int r0 = warpRow + g;
#pragma unroll
            for (int nt = 0; nt < 8; nt++) {
                float2 b0 = *(const float2*)(bias + r0 * NTOK + nt * 8 + c2);
                float2 b1 = *(const float2*)(bias + (r0 + 8) * NTOK + nt * 8 + c2);
                acc[nt][0] = b0.x; acc[nt][1] = b0.y;
                acc[nt][2] = b1.x; acc[nt][3] = b1.y;
            }
        }
        const uint32_t qoff = st + (uint32_t)((warpRow + lrow) * VPITCH + lkb);
#pragma unroll
        for (int ks = 0; ks < 2; ks++) {
            uint32_t Qh[4], Ql[4];
            ldm_x4(Qh, qoff + ks * 32);
            ldm_x4(Ql, qoff + APL_HALF + ks * 32);
#pragma unroll
            for (int nt2 = 0; nt2 < 4; nt2++) {
                uint32_t koff = st + AK_OFF +
                    (uint32_t)((nt2 * 16 + lrow) * VPITCH + lkb) + ks * 32;
                uint32_t Kh[4], Kl[4];
                ldm_x4(Kh, koff);
                ldm_x4(Kl, koff + APL_HALF);
                mma16816(acc[2 * nt2 + 0], Qh, Kh[0], Kh[2]);
                mma16816(acc[2 * nt2 + 1], Qh, Kh[1], Kh[3]);
                mma16816(acc[2 * nt2 + 0], Qh, Kl[0], Kl[2]);
                mma16816(acc[2 * nt2 + 1], Qh, Kl[1], Kl[3]);
                mma16816(acc[2 * nt2 + 0], Ql, Kh[0], Kh[2]);
                mma16816(acc[2 * nt2 + 1], Ql, Kh[1], Kh[3]);
            }
        }

        // ---- softmax + split P ----
#pragma unroll
        for (int half = 0; half < 2; half++) {
            float m = -1e30f;
#pragma unroll
            for (int nt = 0; nt < 8; nt++)
                m = fmaxf(m, fmaxf(acc[nt][2 * half], acc[nt][2 * half + 1]));
            m = fmaxf(m, __shfl_xor_sync(0xffffffffu, m, 1));
            m = fmaxf(m, __shfl_xor_sync(0xffffffffu, m, 2));
            float ssum = 0.0f;
#pragma unroll
            for (int nt = 0; nt < 8; nt++) {
                float e0 = __expf(acc[nt][2 * half] - m);
                float e1 = __expf(acc[nt][2 * half + 1] - m);
                acc[nt][2 * half] = e0; acc[nt][2 * half + 1] = e1;
                ssum += e0 + e1;
            }
            ssum += __shfl_xor_sync(0xffffffffu, ssum, 1);
            ssum += __shfl_xor_sync(0xffffffffu, ssum, 2);
            float inv = 1.0f / ssum;
            int row = warpRow + g + half * 8;
#pragma unroll
            for (int nt = 0; nt < 8; nt++) {
                float v0 = acc[nt][2 * half] * inv;
                float v1 = acc[nt][2 * half + 1] * inv;
                __nv_bfloat16 h0 = __float2bfloat16(v0), h1 = __float2bfloat16(v1);
                float l0 = v0 - __bfloat162float(h0), l1 = v1 - __bfloat162float(h1);
                uint32_t phi = (uint32_t)__bfloat16_as_ushort(h0)
                             | ((uint32_t)__bfloat16_as_ushort(h1) << 16);
                uint32_t plo = pack_bf16_pair(l0, l1);
                uint32_t off = (uint32_t)(row * PPITCH + (nt * 8 + c2) * 2);
                *(uint32_t*)(smem + AP_HI + off) = phi;
                *(uint32_t*)(smem + AP_LO + off) = plo;
            }
        }
        __syncwarp();

        // ---- O = P.v ----
        float acc2[4][4];
#pragma unroll
        for (int nt = 0; nt < 4; nt++)
#pragma unroll
            for (int e = 0; e < 4; e++) acc2[nt][e] = 0.0f;

        const uint32_t poff = (uint32_t)((warpRow + lrow) * PPITCH + lkb);
        const uint32_t voff = (uint32_t)((lid & 7) * VPITCH + (lid >> 3) * 16);
#pragma unroll
        for (int ks = 0; ks < 4; ks++) {
            uint32_t Ph[4], Pl[4];
            ldm_x4(Ph, sb + AP_HI + poff + ks * 32);
            ldm_x4(Pl, sb + AP_LO + poff + ks * 32);
            uint32_t v0 = st + AV_OFF + voff + (uint32_t)(ks * 16) * VPITCH;
            uint32_t Vh0[4], Vh1[4], Vl0[4], Vl1[4];
            ldm_x4_t(Vh0, v0);
            ldm_x4_t(Vh1, v0 + 8 * VPITCH);
            ldm_x4_t(Vl0, v0 + APL_HALF);
            ldm_x4_t(Vl1, v0 + APL_HALF + 8 * VPITCH);
#pragma unroll
            for (int nt = 0; nt < 4; nt++) {
                mma16816(acc2[nt], Ph, Vh0[nt], Vh1[nt]);
                mma16816(acc2[nt], Ph, Vl0[nt], Vl1[nt]);
                mma16816(acc2[nt], Pl, Vh0[nt], Vh1[nt]);
            }
        }

        // ---- store O planes ----
        const int r0 = warpRow + g;
#pragma unroll
        for (int nt = 0; nt < 4; nt++) {
            int d = nt * 8 + c2;
            size_t base0 = ((size_t)b * NTOK + r0) * DIM + h * HDIM + d;
            size_t base1 = ((size_t)b * NTOK + r0 + 8) * DIM + h * HDIM + d;
            store_split2(acc2[nt][0], acc2[nt][1], g_atth + base0, g_attl + base0);
            store_split2(acc2[nt][2], acc2[nt][3], g_atth + base1, g_attl + base1);
        }
        __syncthreads();
    }
}

// ---------------------------------------------------------------------------
// Launch
// ---------------------------------------------------------------------------
extern "C" void kernel_launch(void* const* d_in, const int* in_sizes, int n_in,
                              void* d_out, int out_size) {
    (void)in_sizes; (void)n_in; (void)out_size;
    const float* x      = (const float*)d_in[0];
    const float* qkv_w  = (const float*)d_in[1];
    const float* qkv_b  = (const float*)d_in[2];
    const float* proj_w = (const float*)d_in[3];
    const float* proj_b = (const float*)d_in[4];
    const float* rpb    = (const float*)d_in[5];
    const int*   relid  = (const int*)d_in[6];
    float* out = (float*)d_out;

    cudaFuncSetAttribute(gemm_kernel<9, true>,
                         cudaFuncAttributeMaxDynamicSharedMemorySize, SMEM_BYTES);
    cudaFuncSetAttribute(gemm_kernel<3, false>,
                         cudaFuncAttributeMaxDynamicSharedMemorySize, SMEM_BYTES);
    cudaFuncSetAttribute(attn_kernel,
                         cudaFuncAttributeMaxDynamicSharedMemorySize, ATT_SMEM);

    bias_kernel<<<(HEADS * NTOK * NTOK + 255) / 256, 256>>>(rpb, relid);
    wsplit_kernel<<<(576 * 192 + 255) / 256, 256>>>(qkv_w, proj_w);
    gemm_kernel<9, true><<<NWIN * NTOK / 128, 256, SMEM_BYTES>>>(x, qkv_b, nullptr);
    attn_kernel<<<NWIN, 128, ATT_SMEM>>>();
    gemm_kernel<3, false><<<NWIN * NTOK / 128, 256, SMEM_BYTES>>>(nullptr, proj_b, out);
}

// round 17
// speedup vs baseline: 1.1366x; 1.1366x over previous
#include <cuda_runtime.h>
#include <cuda_bf16.h>
#include <cstdint>

#define DIM   192
#define HEADS 6
#define HDIM  32
#define NTOK  64
#define NWIN  4096

// ---------------------------------------------------------------------------
// Scratch (static device globals — no allocation in kernel_launch)
// ---------------------------------------------------------------------------
__device__ __nv_bfloat16 g_qkvh[(size_t)NWIN * 3 * HEADS * NTOK * HDIM];
__device__ __nv_bfloat16 g_qkvl[(size_t)NWIN * 3 * HEADS * NTOK * HDIM];
__device__ __nv_bfloat16 g_atth[(size_t)NWIN * NTOK * DIM];
__device__ __nv_bfloat16 g_attl[(size_t)NWIN * NTOK * DIM];
__device__ float g_bias[HEADS * NTOK * NTOK];
// pre-split weights: [plane hi/lo][col][k] bf16, k contiguous
__device__ __nv_bfloat16 g_wq[2][576 * 192];
__device__ __nv_bfloat16 g_wp[2][192 * 192];

// ---------------------------------------------------------------------------
// Helpers
// ---------------------------------------------------------------------------
__device__ __forceinline__ uint32_t smem_to_u32(const void* smem_ptr) {
    uint32_t addr;
    asm("{ .reg .u64 tmp; cvta.to.shared.u64 tmp, %1; cvt.u32.u64 %0, tmp; }"
        : "=r"(addr) : "l"(smem_ptr));
    return addr;
}
__device__ __forceinline__ void ldm_x4(uint32_t* r, uint32_t addr) {
    asm volatile("ldmatrix.sync.aligned.m8n8.x4.shared.b16 {%0,%1,%2,%3}, [%4];"
                 : "=r"(r[0]), "=r"(r[1]), "=r"(r[2]), "=r"(r[3]) : "r"(addr));
}
__device__ __forceinline__ void ldm_x4_t(uint32_t* r, uint32_t addr) {
    asm volatile("ldmatrix.sync.aligned.m8n8.x4.trans.shared.b16 {%0,%1,%2,%3}, [%4];"
                 : "=r"(r[0]), "=r"(r[1]), "=r"(r[2]), "=r"(r[3]) : "r"(addr));
}
__device__ __forceinline__ void mma16816(float* c, const uint32_t* a,
                                         uint32_t b0, uint32_t b1) {
    asm volatile(
        "mma.sync.aligned.m16n8k16.row.col.f32.bf16.bf16.f32 "
        "{%0,%1,%2,%3}, {%4,%5,%6,%7}, {%8,%9}, {%0,%1,%2,%3};"
        : "+f"(c[0]), "+f"(c[1]), "+f"(c[2]), "+f"(c[3])
        : "r"(a[0]), "r"(a[1]), "r"(a[2]), "r"(a[3]), "r"(b0), "r"(b1));
}
__device__ __forceinline__ void cp16(uint32_t saddr, const void* gptr) {
    asm volatile("cp.async.cg.shared.global [%0], [%1], 16;"
                 :: "r"(saddr), "l"(gptr));
}
#define CP_COMMIT() asm volatile("cp.async.commit_group;" ::: "memory")
#define CP_WAIT0()  asm volatile("cp.async.wait_group 0;" ::: "memory")

// bf16 hi/lo split of 4 floats, packed for 8-byte smem stores
__device__ __forceinline__ void split4(float4 v, uint2& hi, uint2& lo) {
    __nv_bfloat16 hx = __float2bfloat16(v.x), hy = __float2bfloat16(v.y);
    __nv_bfloat16 hz = __float2bfloat16(v.z), hw = __float2bfloat16(v.w);
    float rx = v.x - __bfloat162float(hx), ry = v.y - __bfloat162float(hy);
    float rz = v.z - __bfloat162float(hz), rw = v.w - __bfloat162float(hw);
    __nv_bfloat16 lx = __float2bfloat16(rx), ly = __float2bfloat16(ry);
    __nv_bfloat16 lz = __float2bfloat16(rz), lw = __float2bfloat16(rw);
    hi.x = (uint32_t)__bfloat16_as_ushort(hx) | ((uint32_t)__bfloat16_as_ushort(hy) << 16);
    hi.y = (uint32_t)__bfloat16_as_ushort(hz) | ((uint32_t)__bfloat16_as_ushort(hw) << 16);
    lo.x = (uint32_t)__bfloat16_as_ushort(lx) | ((uint32_t)__bfloat16_as_ushort(ly) << 16);
    lo.y = (uint32_t)__bfloat16_as_ushort(lz) | ((uint32_t)__bfloat16_as_ushort(lw) << 16);
}
__device__ __forceinline__ uint32_t pack_bf16_pair(float a, float b) {
    __nv_bfloat16 ha = __float2bfloat16(a), hb = __float2bfloat16(b);
    return (uint32_t)__bfloat16_as_ushort(ha) | ((uint32_t)__bfloat16_as_ushort(hb) << 16);
}
__device__ __forceinline__ void store_split2(float v0, float v1,
                                             __nv_bfloat16* hp, __nv_bfloat16* lp) {
    __nv_bfloat16 h0 = __float2bfloat16(v0), h1 = __float2bfloat16(v1);
    float l0 = v0 - __bfloat162float(h0), l1 = v1 - __bfloat162float(h1);
    __nv_bfloat162 hv; hv.x = h0; hv.y = h1;
    __nv_bfloat162 lv; lv.x = __float2bfloat16(l0); lv.y = __float2bfloat16(l1);
    *(__nv_bfloat162*)hp = hv;
    *(__nv_bfloat162*)lp = lv;
}

// ---------------------------------------------------------------------------
// K0a: bias materialization
// ---------------------------------------------------------------------------
__global__ void bias_kernel(const float* __restrict__ rpb,
                            const int*   __restrict__ rel_idx) {
    int idx = blockIdx.x * blockDim.x + threadIdx.x;
    if (idx < HEADS * NTOK * NTOK) {
        int h = idx / (NTOK * NTOK);
        int r = idx % (NTOK * NTOK);
        g_bias[idx] = rpb[rel_idx[r] * HEADS + h];
    }
}
// K0b: weight hi/lo split
__global__ void wsplit_kernel(const float* __restrict__ qkv_w,
                              const float* __restrict__ proj_w) {
    int idx = blockIdx.x * blockDim.x + threadIdx.x;
    if (idx < 576 * 192) {
        float w = qkv_w[idx];
        __nv_bfloat16 hi = __float2bfloat16(w);
        g_wq[0][idx] = hi;
        g_wq[1][idx] = __float2bfloat16(w - __bfloat162float(hi));
    }
    if (idx < 192 * 192) {
        float w = proj_w[idx];
        __nv_bfloat16 hi = __float2bfloat16(w);
        g_wp[0][idx] = hi;
        g_wp[1][idx] = __float2bfloat16(w - __bfloat162float(hi));
    }
}

// ---------------------------------------------------------------------------
// GEMM shared layout: pitch 400B (192 bf16 + 8 pad)
// ---------------------------------------------------------------------------
#define PITCH      400u
#define A_LO_OFF   51200u
#define B_BASE     102400u
#define B_LO_OFF   25600u
#define B_STRIDE   51200u
#define SMEM_BYTES 204800u

// ---------------------------------------------------------------------------
// GEMM (proven shape): 256 threads, 8 warps as 4x2, warp tile 32x32.
// C[128 rows, CT*64 cols] = A(.,192) @ W^T + b  (bf16 hi/lo, 3 products)
// ---------------------------------------------------------------------------
template<int CT, bool QKV>
__global__ void __launch_bounds__(256, 1)
gemm_kernel(const float* __restrict__ Ain,
            const float* __restrict__ bvec, float* __restrict__ Out)
{
    extern __shared__ __align__(16) char smem[];
    const uint32_t sb = smem_to_u32(smem);
    const int tid = threadIdx.x;
    const int wid = tid >> 5, lid = tid & 31;
    const int rowBase = blockIdx.x * 128;
    const int warpRow = (wid & 3) * 32;
    const int warpCol = (wid >> 2) * 32;

    const __nv_bfloat16* whi = QKV ? g_wq[0] : g_wp[0];
    const __nv_bfloat16* wlo = QKV ? g_wq[1] : g_wp[1];

    // prologue: cp.async B tile 0 into stage 0 (3072 cp16)
#pragma unroll
    for (int i = 0; i < 12; i++) {
        int idx = tid + i * 256;
        int plane = idx / 1536, rem = idx - plane * 1536;
        int r = rem / 24, c = rem % 24;
        const __nv_bfloat16* src = (plane ? wlo : whi) + (size_t)r * 192 + c * 8;
        cp16(sb + B_BASE + plane * B_LO_OFF + r * PITCH + c * 16, src);
    }

    // A tile
    if (QKV) {
#pragma unroll
        for (int i = 0; i < 24; i++) {
            int idx = tid + i * 256;
            int r = idx / 48, k4 = (idx % 48) * 4;
            float4 v = *(const float4*)(Ain + (size_t)(rowBase + r) * DIM + k4);
            uint2 hi, lo; split4(v, hi, lo);
            *(uint2*)(smem + r * PITCH + k4 * 2) = hi;
            *(uint2*)(smem + A_LO_OFF + r * PITCH + k4 * 2) = lo;
        }
    } else {
#pragma unroll
        for (int i = 0; i < 24; i++) {
            int idx = tid + i * 256;              // 6144 cp16
            int plane = idx / 3072, rem = idx - plane * 3072;
            int r = rem / 24, c = rem % 24;
            const __nv_bfloat16* src =
                (plane ? g_attl : g_atth) + (size_t)(rowBase + r) * 192 + c * 8;
            cp16(sb + plane * A_LO_OFF + r * PITCH + c * 16, src);
        }
    }
    CP_COMMIT();
    CP_WAIT0();
    __syncthreads();

    const int lrow = (lid & 7) + ((lid >> 3) & 1) * 8;
    const int lkb  = (lid >> 4) * 16;
    const uint32_t aoff0 = (uint32_t)((warpRow + lrow) * PITCH) + lkb;
    const uint32_t aoff1 = aoff0 + 16 * PITCH;
    const uint32_t boff0 = (uint32_t)((warpCol + lrow) * PITCH) + lkb;
    const uint32_t boff1 = boff0 + 16 * PITCH;

    for (int ct = 0; ct < CT; ct++) {
        if (ct + 1 < CT) {
#pragma unroll
            for (int i = 0; i < 12; i++) {
                int idx = tid + i * 256;
                int plane = idx / 1536, rem = idx - plane * 1536;
                int r = rem / 24, c = rem % 24;
                const __nv_bfloat16* src =
                    (plane ? wlo : whi) + (size_t)((ct + 1) * 64 + r) * 192 + c * 8;
                cp16(sb + B_BASE + (uint32_t)((ct + 1) & 1) * B_STRIDE
                        + plane * B_LO_OFF + r * PITCH + c * 16, src);
            }
            CP_COMMIT();
        }

        float acc[2][4][4];
#pragma unroll
        for (int mt = 0; mt < 2; mt++)
#pragma unroll
            for (int nt = 0; nt < 4; nt++)
#pragma unroll
                for (int e = 0; e < 4; e++) acc[mt][nt][e] = 0.0f;

        const uint32_t bbh = sb + B_BASE + (uint32_t)(ct & 1) * B_STRIDE;
        const uint32_t bbl = bbh + B_LO_OFF;
#pragma unroll
        for (int ks = 0; ks < 12; ks++) {
            uint32_t Ah0[4], Ah1[4], Al0[4], Al1[4];
            uint32_t Bh0[4], Bh1[4], Bl0[4], Bl1[4];
            ldm_x4(Ah0, sb + aoff0 + ks * 32);
            ldm_x4(Ah1, sb + aoff1 + ks * 32);
            ldm_x4(Al0, sb + A_LO_OFF + aoff0 + ks * 32);
            ldm_x4(Al1, sb + A_LO_OFF + aoff1 + ks * 32);
            ldm_x4(Bh0, bbh + boff0 + ks * 32);
            ldm_x4(Bh1, bbh + boff1 + ks * 32);
            ldm_x4(Bl0, bbl + boff0 + ks * 32);
            ldm_x4(Bl1, bbl + boff1 + ks * 32);
            mma16816(acc[0][0], Ah0, Bh0[0], Bh0[2]);
            mma16816(acc[0][1], Ah0, Bh0[1], Bh0[3]);
            mma16816(acc[0][2], Ah0, Bh1[0], Bh1[2]);
            mma16816(acc[0][3], Ah0, Bh1[1], Bh1[3]);
            mma16816(acc[1][0], Ah1, Bh0[0], Bh0[2]);
            mma16816(acc[1][1], Ah1, Bh0[1], Bh0[3]);
            mma16816(acc[1][2], Ah1, Bh1[0], Bh1[2]);
            mma16816(acc[1][3], Ah1, Bh1[1], Bh1[3]);
            mma16816(acc[0][0], Ah0, Bl0[0], Bl0[2]);
            mma16816(acc[0][1], Ah0, Bl0[1], Bl0[3]);
            mma16816(acc[0][2], Ah0, Bl1[0], Bl1[2]);
            mma16816(acc[0][3], Ah0, Bl1[1], Bl1[3]);
            mma16816(acc[1][0], Ah1, Bl0[0], Bl0[2]);
            mma16816(acc[1][1], Ah1, Bl0[1], Bl0[3]);
            mma16816(acc[1][2], Ah1, Bl1[0], Bl1[2]);
            mma16816(acc[1][3], Ah1, Bl1[1], Bl1[3]);
            mma16816(acc[0][0], Al0, Bh0[0], Bh0[2]);
            mma16816(acc[0][1], Al0, Bh0[1], Bh0[3]);
            mma16816(acc[0][2], Al0, Bh1[0], Bh1[2]);
            mma16816(acc[0][3], Al0, Bh1[1], Bh1[3]);
            mma16816(acc[1][0], Al1, Bh0[0], Bh0[2]);
            mma16816(acc[1][1], Al1, Bh0[1], Bh0[3]);
            mma16816(acc[1][2], Al1, Bh1[0], Bh1[2]);
            mma16816(acc[1][3], Al1, Bh1[1], Bh1[3]);
        }

        // epilogue
        const int g  = lid >> 2;
        const int c2 = (lid & 3) * 2;
#pragma unroll
        for (int mt = 0; mt < 2; mt++) {
            const int r0 = rowBase + warpRow + mt * 16 + g;
#pragma unroll
            for (int nt = 0; nt < 4; nt++) {
                const int colg = ct * 64 + warpCol + nt * 8 + c2;
                const float bv0 = bvec[colg], bv1 = bvec[colg + 1];
                if (QKV) {
                    const int s = colg / DIM, rem = colg % DIM;
                    const int h = rem >> 5, dd = rem & 31;
                    const float mul = (s == 0) ? 0.17677669529663687f : 1.0f;
#pragma unroll
                    for (int hh = 0; hh < 2; hh++) {
                        const int row = r0 + hh * 8;
                        const int bw = row >> 6, n = row & 63;
                        size_t base = ((((size_t)bw * 3 + s) * HEADS + h) * NTOK + n) * HDIM + dd;
                        store_split2((acc[mt][nt][hh * 2 + 0] + bv0) * mul,
                                     (acc[mt][nt][hh * 2 + 1] + bv1) * mul,
                                     g_qkvh + base, g_qkvl + base);
                    }
                } else {
#pragma unroll
                    for (int hh = 0; hh < 2; hh++) {
                        const int row = r0 + hh * 8;
                        float2 o = make_float2(acc[mt][nt][hh * 2 + 0] + bv0,
                                               acc[mt][nt][hh * 2 + 1] + bv1);
                        *(float2*)(Out + (size_t)row * DIM + colg) = o;
                    }
                }
            }
        }
        if (ct + 1 < CT) {
            CP_WAIT0();
            __syncthreads();
        }
    }
}

// ---------------------------------------------------------------------------
// Attention: one block (128 thr, 4 warps) per (window, head). P kept entirely
// in registers: S C-fragments repack directly into PV A-fragments.
// Shared: only q/k/v hi+lo planes = 30720 bytes -> high residency.
// ---------------------------------------------------------------------------
#define APL_HALF 5120u
#define AK_OFF   10240u
#define AV_OFF   20480u
#define ATT_SMEM 30720u
#define VPITCH 80u

__global__ void __launch_bounds__(128, 5) attn_kernel() {
    extern __shared__ __align__(16) char smem[];
    const uint32_t sb = smem_to_u32(smem);
    const int tid = threadIdx.x;
    const int wid = tid >> 5, lid = tid & 31;
    const int bh = blockIdx.x;
    const int b = bh / HEADS, h = bh % HEADS;

    // cp.async the 6 planes (q/k/v x hi/lo): 1536 cp16 over 128 threads
#pragma unroll
    for (int i = 0; i < 12; i++) {
        int idx = tid + i * 128;
        int plane = idx >> 8;                  // 0..5, 256 cp16 per plane
        int rem = idx & 255;
        int n = rem >> 2, c = rem & 3;
        int mat = plane >> 1, lo = plane & 1;
        const __nv_bfloat16* src =
            (lo ? g_qkvl : g_qkvh) +
            ((((size_t)b * 3 + mat) * HEADS + h) * NTOK + n) * HDIM + c * 8;
        cp16(sb + (uint32_t)mat * 10240u + (uint32_t)lo * APL_HALF
                + (uint32_t)n * VPITCH + (uint32_t)c * 16u, src);
    }
    CP_COMMIT();
    CP_WAIT0();
    __syncthreads();

    const int warpRow = wid * 16;
    const int lrow = (lid & 7) + ((lid >> 3) & 1) * 8;
    const int lkb  = (lid >> 4) * 16;
    const int g  = lid >> 2;
    const int c2 = (lid & 3) * 2;

    // ---- S = q.k^T + bias ----
    float acc[8][4];
    {
        const float* bias = g_bias + h * (NTOK * NTOK);
        const int r0 = warpRow + g;
#pragma unroll
        for (int nt = 0; nt < 8; nt++) {
            float2 b0 = *(const float2*)(bias + r0 * NTOK + nt * 8 + c2);
            float2 b1 = *(const float2*)(bias + (r0 + 8) * NTOK + nt * 8 + c2);
            acc[nt][0] = b0.x; acc[nt][1] = b0.y;
            acc[nt][2] = b1.x; acc[nt][3] = b1.y;
        }
    }
    const uint32_t qoff = sb + (uint32_t)((warpRow + lrow) * VPITCH + lkb);
#pragma unroll
    for (int ks = 0; ks < 2; ks++) {
        uint32_t Qh[4], Ql[4];
        ldm_x4(Qh, qoff + ks * 32);
        ldm_x4(Ql, qoff + APL_HALF + ks * 32);
#pragma unroll
        for (int nt2 = 0; nt2 < 4; nt2++) {
            uint32_t koff = sb + AK_OFF +
                (uint32_t)((nt2 * 16 + lrow) * VPITCH + lkb) + ks * 32;
            uint32_t Kh[4], Kl[4];
            ldm_x4(Kh, koff);
            ldm_x4(Kl, koff + APL_HALF);
            mma16816(acc[2 * nt2 + 0], Qh, Kh[0], Kh[2]);
            mma16816(acc[2 * nt2 + 1], Qh, Kh[1], Kh[3]);
            mma16816(acc[2 * nt2 + 0], Qh, Kl[0], Kl[2]);
            mma16816(acc[2 * nt2 + 1], Qh, Kl[1], Kl[3]);
            mma16816(acc[2 * nt2 + 0], Ql, Kh[0], Kh[2]);
            mma16816(acc[2 * nt2 + 1], Ql, Kh[1], Kh[3]);
        }
    }

    // ---- softmax, packing P hi/lo straight into A-fragment registers ----
    // Ph[nt][0] = row g pair (cols 2c,2c+1 of n-tile nt), [1] = row g+8 pair.
    uint32_t Ph[8][2], Pl[8][2];
#pragma unroll
    for (int half = 0; half < 2; half++) {
        float m = -1e30f;
#pragma unroll
        for (int nt = 0; nt < 8; nt++)
            m = fmaxf(m, fmaxf(acc[nt][2 * half], acc[nt][2 * half + 1]));
        m = fmaxf(m, __shfl_xor_sync(0xffffffffu, m, 1));
        m = fmaxf(m, __shfl_xor_sync(0xffffffffu, m, 2));
        float ssum = 0.0f;
#pragma unroll
        for (int nt = 0; nt < 8; nt++) {
            float e0 = __expf(acc[nt][2 * half] - m);
            float e1 = __expf(acc[nt][2 * half + 1] - m);
            acc[nt][2 * half] = e0; acc[nt][2 * half + 1] = e1;
            ssum += e0 + e1;
        }
        ssum += __shfl_xor_sync(0xffffffffu, ssum, 1);
        ssum += __shfl_xor_sync(0xffffffffu, ssum, 2);
        float inv = 1.0f / ssum;
#pragma unroll
        for (int nt = 0; nt < 8; nt++) {
            float v0 = acc[nt][2 * half] * inv;
            float v1 = acc[nt][2 * half + 1] * inv;
            __nv_bfloat16 h0 = __float2bfloat16(v0), h1 = __float2bfloat16(v1);
            float l0 = v0 - __bfloat162float(h0), l1 = v1 - __bfloat162float(h1);
            Ph[nt][half] = (uint32_t)__bfloat16_as_ushort(h0)
                         | ((uint32_t)__bfloat16_as_ushort(h1) << 16);
            Pl[nt][half] = pack_bf16_pair(l0, l1);
        }
    }

    // ---- O = P.v  (A-frags from registers; V via ldmatrix.trans) ----
    float acc2[4][4];
#pragma unroll
    for (int nt = 0; nt < 4; nt++)
#pragma unroll
        for (int e = 0; e < 4; e++) acc2[nt][e] = 0.0f;

    const uint32_t voff = (uint32_t)((lid & 7) * VPITCH + (lid >> 3) * 16);
#pragma unroll
    for (int kt = 0; kt < 4; kt++) {
        uint32_t Ah[4] = { Ph[2 * kt][0], Ph[2 * kt][1],
                           Ph[2 * kt + 1][0], Ph[2 * kt + 1][1] };
        uint32_t Al[4] = { Pl[2 * kt][0], Pl[2 * kt][1],
                           Pl[2 * kt + 1][0], Pl[2 * kt + 1][1] };
        uint32_t v0 = sb + AV_OFF + voff + (uint32_t)(kt * 16) * VPITCH;
        uint32_t Vh0[4], Vh1[4], Vl0[4], Vl1[4];
        ldm_x4_t(Vh0, v0);
        ldm_x4_t(Vh1, v0 + 8 * VPITCH);
        ldm_x4_t(Vl0, v0 + APL_HALF);
        ldm_x4_t(Vl1, v0 + APL_HALF + 8 * VPITCH);
#pragma unroll
        for (int nt = 0; nt < 4; nt++) {
            mma16816(acc2[nt], Ah, Vh0[nt], Vh1[nt]);
            mma16816(acc2[nt], Ah, Vl0[nt], Vl1[nt]);
            mma16816(acc2[nt], Al, Vh0[nt], Vh1[nt]);
        }
    }

    // ---- store O as bf16 hi/lo planes for proj ----
    const int r0 = warpRow + g;
#pragma unroll
    for (int nt = 0; nt < 4; nt++) {
        int d = nt * 8 + c2;
        size_t base0 = ((size_t)b * NTOK + r0) * DIM + h * HDIM + d;
        size_t base1 = ((size_t)b * NTOK + r0 + 8) * DIM + h * HDIM + d;
        store_split2(acc2[nt][0], acc2[nt][1], g_atth + base0, g_attl + base0);
        store_split2(acc2[nt][2], acc2[nt][3], g_atth + base1, g_attl + base1);
    }
}

// ---------------------------------------------------------------------------
// Launch
// ---------------------------------------------------------------------------
extern "C" void kernel_launch(void* const* d_in, const int* in_sizes, int n_in,
                              void* d_out, int out_size) {
    (void)in_sizes; (void)n_in; (void)out_size;
    const float* x      = (const float*)d_in[0];
    const float* qkv_w  = (const float*)d_in[1];
    const float* qkv_b  = (const float*)d_in[2];
    const float* proj_w = (const float*)d_in[3];
    const float* proj_b = (const float*)d_in[4];
    const float* rpb    = (const float*)d_in[5];
    const int*   relid  = (const int*)d_in[6];
    float* out = (float*)d_out;

    cudaFuncSetAttribute(gemm_kernel<9, true>,
                         cudaFuncAttributeMaxDynamicSharedMemorySize, SMEM_BYTES);
    cudaFuncSetAttribute(gemm_kernel<3, false>,
                         cudaFuncAttributeMaxDynamicSharedMemorySize, SMEM_BYTES);
    cudaFuncSetAttribute(attn_kernel,
                         cudaFuncAttributeMaxDynamicSharedMemorySize, ATT_SMEM);

    bias_kernel<<<(HEADS * NTOK * NTOK + 255) / 256, 256>>>(rpb, relid);
    wsplit_kernel<<<(576 * 192 + 255) / 256, 256>>>(qkv_w, proj_w);
    gemm_kernel<9, true><<<NWIN * NTOK / 128, 256, SMEM_BYTES>>>(x, qkv_b, nullptr);
    attn_kernel<<<NWIN * HEADS, 128, ATT_SMEM>>>();
    gemm_kernel<3, false><<<NWIN * NTOK / 128, 256, SMEM_BYTES>>>(nullptr, proj_b, out);
}